// round 3
// baseline (speedup 1.0000x reference)
#include <cuda_runtime.h>
#include <cuda_bf16.h>

#define BATCH 32
#define NAG   6
#define KS    256
#define QS    256
#define CHW   (512*32*32)       /* 524288 floats per (b,n) slab */
#define V4PB  (CHW/4)           /* 131072 float4 per (b,n) slab */

// Scratch (allocation-free rule: __device__ global)
__device__ float g_attn[BATCH * NAG];

// ---------------------------------------------------------------------------
// Kernel 1 (fused): query = q@W^T + b ; scores = k . query ; sparsemax(N=6)
// One block per batch, 256 threads. Each thread computes one query element
// with 4 independent accumulators (64 float4 loads batch into high MLP).
// ---------------------------------------------------------------------------
__global__ void __launch_bounds__(256)
attn_kernel(const float* __restrict__ q,
            const float* __restrict__ k,
            const float* __restrict__ W,
            const float* __restrict__ bias,
            float* __restrict__ out_attn,
            int write_attn) {
    const int b = blockIdx.x;
    const int t = threadIdx.x;

    __shared__ float4 sq4[QS / 4];
    __shared__ float  squery[KS];
    __shared__ float  sscore[NAG];

    if (t < QS / 4) sq4[t] = ((const float4*)(q + (size_t)b * QS))[t];
    __syncthreads();

    // ---- phase 1: query[t] = bias[t] + W[t,:] . q[b,:] ----
    {
        const float4* wrow = (const float4*)(W + (size_t)t * QS);
        float a0 = 0.f, a1 = 0.f, a2 = 0.f, a3 = 0.f;
        #pragma unroll
        for (int d = 0; d < QS / 4; d += 4) {
            float4 w0 = wrow[d + 0], w1 = wrow[d + 1];
            float4 w2 = wrow[d + 2], w3 = wrow[d + 3];
            float4 q0 = sq4[d + 0], q1 = sq4[d + 1];
            float4 q2 = sq4[d + 2], q3 = sq4[d + 3];
            a0 = fmaf(w0.x, q0.x, a0); a0 = fmaf(w0.y, q0.y, a0);
            a0 = fmaf(w0.z, q0.z, a0); a0 = fmaf(w0.w, q0.w, a0);
            a1 = fmaf(w1.x, q1.x, a1); a1 = fmaf(w1.y, q1.y, a1);
            a1 = fmaf(w1.z, q1.z, a1); a1 = fmaf(w1.w, q1.w, a1);
            a2 = fmaf(w2.x, q2.x, a2); a2 = fmaf(w2.y, q2.y, a2);
            a2 = fmaf(w2.z, q2.z, a2); a2 = fmaf(w2.w, q2.w, a2);
            a3 = fmaf(w3.x, q3.x, a3); a3 = fmaf(w3.y, q3.y, a3);
            a3 = fmaf(w3.z, q3.z, a3); a3 = fmaf(w3.w, q3.w, a3);
        }
        squery[t] = bias[t] + (a0 + a1) + (a2 + a3);
    }
    __syncthreads();

    // ---- phase 2: 6 warps compute the 6 agent scores ----
    const int wid = t >> 5, lane = t & 31;
    if (wid < NAG) {
        const float4* kr = (const float4*)(k + (size_t)(b * NAG + wid) * KS);
        const float4* qr = (const float4*)squery;
        float4 k0 = kr[lane],      q0 = qr[lane];
        float4 k1 = kr[lane + 32], q1 = qr[lane + 32];
        float s = k0.x * q0.x + k0.y * q0.y + k0.z * q0.z + k0.w * q0.w
                + k1.x * q1.x + k1.y * q1.y + k1.z * q1.z + k1.w * q1.w;
        #pragma unroll
        for (int o = 16; o; o >>= 1) s += __shfl_xor_sync(0xffffffffu, s, o);
        if (lane == 0) sscore[wid] = s;
    }
    __syncthreads();

    // ---- phase 3: sparsemax over 6 values on thread 0 ----
    if (t == 0) {
        float z[NAG], zs[NAG];
        #pragma unroll
        for (int n = 0; n < NAG; n++) { z[n] = sscore[n]; zs[n] = z[n]; }
        #pragma unroll
        for (int i = 1; i < NAG; i++) {           // insertion sort, descending
            float key = zs[i]; int j = i - 1;
            while (j >= 0 && zs[j] < key) { zs[j + 1] = zs[j]; j--; }
            zs[j + 1] = key;
        }
        float cs[NAG], run = 0.f;
        #pragma unroll
        for (int r = 0; r < NAG; r++) { run += zs[r]; cs[r] = run; }
        int kk = 0;
        #pragma unroll
        for (int r = 1; r <= NAG; r++)
            if (1.0f + (float)r * zs[r - 1] > cs[r - 1]) kk++;
        const float tau = (cs[kk - 1] - 1.0f) / (float)kk;
        #pragma unroll
        for (int n = 0; n < NAG; n++) {
            float p = fmaxf(z[n] - tau, 0.0f);
            g_attn[b * NAG + n] = p;
            if (write_attn) out_attn[b * NAG + n] = p;
        }
    }
}

// ---------------------------------------------------------------------------
// Kernel 2: output[b,:] = sum_n attn[b,n] * v[b,n,:]
// 8 float4 per thread (MLP_p1 = 8). Zero-weight agents skipped (uniform
// branch: whole block shares one batch). Streaming hints: v / out are
// single-use. grid = 2048 blocks, 256 threads, 2048 float4 per block.
// ---------------------------------------------------------------------------
__global__ void __launch_bounds__(256)
wsum_kernel(const float* __restrict__ v, float* __restrict__ out) {
    const int b    = blockIdx.x >> 6;                        // 64 blocks/batch
    const int base = ((blockIdx.x & 63) << 11) + threadIdx.x;   // within slab

    __shared__ float sw[NAG];
    if (threadIdx.x < NAG) sw[threadIdx.x] = g_attn[b * NAG + threadIdx.x];
    __syncthreads();

    const float4* vb = (const float4*)v + (size_t)b * NAG * V4PB + base;

    float4 acc[8];
    #pragma unroll
    for (int i = 0; i < 8; i++) acc[i] = make_float4(0.f, 0.f, 0.f, 0.f);

    #pragma unroll
    for (int n = 0; n < NAG; n++) {
        const float w = sw[n];
        if (w != 0.0f) {
            const float4* p = vb + (size_t)n * V4PB;
            float4 x[8];
            #pragma unroll
            for (int i = 0; i < 8; i++) x[i] = __ldcs(p + (i << 8));
            #pragma unroll
            for (int i = 0; i < 8; i++) {
                acc[i].x = fmaf(w, x[i].x, acc[i].x);
                acc[i].y = fmaf(w, x[i].y, acc[i].y);
                acc[i].z = fmaf(w, x[i].z, acc[i].z);
                acc[i].w = fmaf(w, x[i].w, acc[i].w);
            }
        }
    }

    float4* ob = (float4*)out + (size_t)b * V4PB + base;
    #pragma unroll
    for (int i = 0; i < 8; i++) __stcs(ob + (i << 8), acc[i]);
}

// ---------------------------------------------------------------------------
extern "C" void kernel_launch(void* const* d_in, const int* in_sizes, int n_in,
                              void* d_out, int out_size) {
    const float* q    = (const float*)d_in[0];
    const float* k    = (const float*)d_in[1];
    const float* v    = (const float*)d_in[2];
    const float* W    = (const float*)d_in[3];
    const float* bias = (const float*)d_in[4];

    float* out = (float*)d_out;
    const long long out_main = (long long)BATCH * CHW;        // 16777216
    const int write_attn = (out_size >= out_main + BATCH * NAG) ? 1 : 0;
    float* out_attn = out + out_main;

    attn_kernel<<<BATCH, 256>>>(q, k, W, bias, out_attn, write_attn);

    const int blocks = (BATCH * V4PB) / (256 * 8);            // 2048
    wsum_kernel<<<blocks, 256>>>(v, out);
}